// round 13
// baseline (speedup 1.0000x reference)
#include <cuda_runtime.h>
#include <cstdint>

// Shapes fixed by the dataset
#define CC   64       // classes
#define AA   256      // feature dim
#define NBK  128      // blocks: (b-half, y)
#define NT   512      // 16 warps
#define NROW 4096

#define DST 260       // D row stride: (4c+k)&31 conflict-free fragment reads
#define GST 260       // G row stride: same argument
#define EPI_STRIDE 66

// Fixed-slot scratch (deterministic, no allocation)
__device__ float g_Sh[2 * CC * CC];     // S half-sums [h][y][c]
__device__ float g_blockSums[NBK];
__device__ unsigned g_sync = 0;         // epoch grid-sync counter (monotonic)
__device__ unsigned g_done = 0;         // epoch final-reduction counter
__device__ int g_lab64;

// m16n8k8 tf32 MMA (baseline PTX, compiles for plain sm_103 target)
__device__ __forceinline__ void mma_tf32(float* d,
        uint32_t a0, uint32_t a1, uint32_t a2, uint32_t a3,
        uint32_t b0, uint32_t b1) {
    asm volatile(
        "mma.sync.aligned.m16n8k8.row.col.f32.tf32.tf32.f32 "
        "{%0,%1,%2,%3}, {%4,%5,%6,%7}, {%8,%9}, {%0,%1,%2,%3};"
        : "+f"(d[0]), "+f"(d[1]), "+f"(d[2]), "+f"(d[3])
        : "r"(a0), "r"(a1), "r"(a2), "r"(a3), "r"(b0), "r"(b1));
}

// ---------------------------------------------------------------------------
// Block (h, y): T[c,b] = sum_a D[c,a] G_y[a,b] for b in [h*128, h*128+128).
// 16 warps: warp = (c-parity, n-quad, k-half); 128 MMAs each.  k-split is
// valid because the epilogue scale-by-D is linear in T.
// S_half[h][y][c] = sum_b T[c,b] D[c,b].  Grid-sync; CE over 32 rows; mean.
// ---------------------------------------------------------------------------
extern "C" __global__ void __launch_bounds__(NT) k_fused(
        const float* __restrict__ W, const float* __restrict__ CV,
        const float* __restrict__ pred, const void* __restrict__ labels,
        const float* __restrict__ Lam, float* __restrict__ out) {
    extern __shared__ float sm[];
    float* Dsf = sm;                       // [64][260]  D = W - w_y
    float* Gs  = sm + CC * DST;            // [128][260] G rows h*128..+127
    float* epi = Gs + 128 * GST;           // [16][66] warp partials
    __shared__ float ws[16];
    __shared__ unsigned s_flag;

    const int h    = blockIdx.x;
    const int y    = blockIdx.y;
    const int tid  = threadIdx.x;
    const int w    = tid >> 5;
    const int lane = tid & 31;
    const int g    = lane >> 2;   // fragment groupID
    const int t    = lane & 3;    // fragment threadID_in_group
    const int bid  = y * 2 + h;

    // Warp role: c-parity, n-quad, k-half
    const int par = w & 1;
    const int ntq = (w >> 1) & 3;
    const int kh  = w >> 3;
    const int mtb = par * 2;
    const int ntb = ntq * 4;

    // Labels may be int32 (JAX default) or int64 (x64): range-check 8 int64
    // interpretations; int32 data aliases high words and blows the range.
    if (bid == 0 && tid == 0) {
        int ok = 1;
#pragma unroll
        for (int i = 0; i < 8; i++) {
            long long v = ((const long long*)labels)[i];
            if (v < 0 || v >= CC) ok = 0;
        }
        g_lab64 = ok;
    }

    // ---- Bulk load: D (64x256, 8 f4/thread) + G-half (128x256, 16 f4/thr)
    const float* wy = W + y * AA;
    for (int i = tid; i < CC * (AA / 4); i += NT) {
        const int c  = i >> 6;
        const int a4 = (i & 63) << 2;
        float4 wv = *(const float4*)(W + c * AA + a4);
        float4 yv = *(const float4*)(wy + a4);
        float4 d;
        d.x = wv.x - yv.x; d.y = wv.y - yv.y;
        d.z = wv.z - yv.z; d.w = wv.w - yv.w;
        *(float4*)(&Dsf[c * DST + a4]) = d;
    }
    const float* G = CV + (size_t)y * (AA * AA) + (size_t)h * 128 * AA;
    for (int i = tid; i < 128 * (AA / 4); i += NT) {
        const int r   = i >> 6;
        const int seg = (i & 63) << 2;
        float4 v = *(const float4*)(G + r * AA + seg);
        *(float4*)(&Gs[r * GST + seg]) = v;
    }
    __syncthreads();   // the only barrier before the epilogue

    // ---- Barrier-free MMA loop over this warp's k-half (16 k-steps) ----
    float acc[2][4][4];
#pragma unroll
    for (int mi = 0; mi < 2; mi++)
#pragma unroll
        for (int ni = 0; ni < 4; ni++)
#pragma unroll
            for (int r = 0; r < 4; r++) acc[mi][ni][r] = 0.f;

#pragma unroll 4
    for (int ks = 0; ks < 16; ks++) {
        const int kg = kh * 128 + ks * 8;
        uint32_t af[2][4];
#pragma unroll
        for (int mi = 0; mi < 2; mi++) {
            const int c0 = (mtb + mi) * 16 + g;
            af[mi][0] = __float_as_uint(Dsf[c0 * DST + kg + t]);
            af[mi][1] = __float_as_uint(Dsf[(c0 + 8) * DST + kg + t]);
            af[mi][2] = __float_as_uint(Dsf[c0 * DST + kg + t + 4]);
            af[mi][3] = __float_as_uint(Dsf[(c0 + 8) * DST + kg + t + 4]);
        }
        uint32_t bf[4][2];
#pragma unroll
        for (int ni = 0; ni < 4; ni++) {
            const int n = (ntb + ni) * 8 + g;
            bf[ni][0] = __float_as_uint(Gs[n * GST + kg + t]);
            bf[ni][1] = __float_as_uint(Gs[n * GST + kg + t + 4]);
        }
#pragma unroll
        for (int mi = 0; mi < 2; mi++)
#pragma unroll
            for (int ni = 0; ni < 4; ni++)
                mma_tf32(acc[mi][ni], af[mi][0], af[mi][1], af[mi][2],
                         af[mi][3], bf[ni][0], bf[ni][1]);
    }

    // ---- Epilogue: scale k-half partial by D, reduce, stage ------------
    // acc regs: [0]=(c0,b0) [1]=(c0,b0+1) [2]=(c0+8,b0) [3]=(c0+8,b0+1),
    // c0 = mt*16+g, b0 = (ntb+ni)*8 + 2t  (b global = h*128 + b0).
#pragma unroll
    for (int mi = 0; mi < 2; mi++) {
        const int c0 = (mtb + mi) * 16 + g;
        const int c1 = c0 + 8;
        float s0 = 0.f, s1 = 0.f;
#pragma unroll
        for (int ni = 0; ni < 4; ni++) {
            const int bg = h * 128 + (ntb + ni) * 8 + 2 * t;
            s0 += acc[mi][ni][0] * Dsf[c0 * DST + bg]
                + acc[mi][ni][1] * Dsf[c0 * DST + bg + 1];
            s1 += acc[mi][ni][2] * Dsf[c1 * DST + bg]
                + acc[mi][ni][3] * Dsf[c1 * DST + bg + 1];
        }
        s0 += __shfl_xor_sync(0xffffffffu, s0, 1);
        s0 += __shfl_xor_sync(0xffffffffu, s0, 2);
        s1 += __shfl_xor_sync(0xffffffffu, s1, 1);
        s1 += __shfl_xor_sync(0xffffffffu, s1, 2);
        if (t == 0) {
            epi[w * EPI_STRIDE + c0] = s0;
            epi[w * EPI_STRIDE + c1] = s1;
        }
    }
    __syncthreads();
    if (tid < CC) {   // combine the 8 warps matching this c's parity
        const int cp = tid >> 5;
        float s = 0.f;
#pragma unroll
        for (int j = 0; j < 8; j++) {
            const int ww = cp + 2 * (j & 3) + 8 * (j >> 2);
            s += epi[ww * EPI_STRIDE + tid];
        }
        g_Sh[(h * CC + y) * CC + tid] = s;
    }

    // ---- Epoch grid-sync (monotonic; 128 blocks all co-resident @1/SM) --
    __syncthreads();
    if (tid == 0) {
        __threadfence();
        unsigned old = atomicAdd(&g_sync, 1u);
        unsigned target = (old / NBK + 1u) * NBK;
        while (*(volatile unsigned*)&g_sync < target) { }
        __threadfence();
    }
    __syncthreads();

    // ---- Phase 2: softmax-CE over rows [bid*32, bid*32+32) --------------
    const int   lab64 = g_lab64;
    const float lam   = 0.5f * __ldg(Lam);
    const float* S0 = g_Sh;               // h = 0 halves
    const float* S1 = g_Sh + CC * CC;     // h = 1 halves

    float wsum = 0.f;
#pragma unroll
    for (int rr = 0; rr < 2; rr++) {
        const int n = bid * 32 + w * 2 + rr;
        const int yl = lab64 ? (int)((const long long*)labels)[n]
                             : ((const int*)labels)[n];
        const float* p = pred + (size_t)n * CC;
        const int c2 = lane + 32;

        float a1 = p[lane] + lam * (S0[yl * CC + lane] + S1[yl * CC + lane]);
        float a2 = p[c2]   + lam * (S0[yl * CC + c2]   + S1[yl * CC + c2]);

        float m = fmaxf(a1, a2);
#pragma unroll
        for (int off = 16; off; off >>= 1)
            m = fmaxf(m, __shfl_xor_sync(0xffffffffu, m, off));
        float e = __expf(a1 - m) + __expf(a2 - m);
#pragma unroll
        for (int off = 16; off; off >>= 1)
            e += __shfl_xor_sync(0xffffffffu, e, off);
        float ay = __shfl_sync(0xffffffffu, (yl < 32) ? a1 : a2, yl & 31);
        wsum += m + __logf(e) - ay;
    }

    if (lane == 0) ws[w] = wsum;
    __syncthreads();
    if (tid == 0) {
        float s = 0.f;
#pragma unroll
        for (int i = 0; i < 16; i++) s += ws[i];
        g_blockSums[bid] = s;
        __threadfence();
        unsigned old = atomicAdd(&g_done, 1u);
        s_flag = ((old % NBK) == NBK - 1u) ? 1u : 0u;
    }
    __syncthreads();

    if (s_flag && w == 0) {   // last block: fixed-order sum of 128 partials
        __threadfence();
        float v = 0.f;
#pragma unroll
        for (int k = 0; k < NBK / 32; k++)
            v += g_blockSums[k * 32 + lane];
#pragma unroll
        for (int off = 16; off; off >>= 1)
            v += __shfl_xor_sync(0xffffffffu, v, off);
        if (lane == 0)
            out[0] = v / (float)NROW;
    }
}

// ---------------------------------------------------------------------------
// Inputs (metadata order): fc_weight[C,A] f32, features (unused), pred[N,C] f32,
// labels[N] i32/i64, Lambda[1] f32, covariance_sample[C,A,A] f32.
// ---------------------------------------------------------------------------
extern "C" void kernel_launch(void* const* d_in, const int* in_sizes, int n_in,
                              void* d_out, int out_size) {
    const float* W      = (const float*)d_in[0];
    const float* pred   = (const float*)d_in[2];
    const void*  labels = d_in[3];
    const float* Lam    = (const float*)d_in[4];
    const float* CV     = (const float*)d_in[5];

    const int smem_bytes = (CC * DST + 128 * GST + 16 * EPI_STRIDE)
                         * (int)sizeof(float);   // ~204 KB
    cudaFuncSetAttribute(k_fused, cudaFuncAttributeMaxDynamicSharedMemorySize,
                         smem_bytes);
    k_fused<<<dim3(2, CC), NT, smem_bytes>>>(W, CV, pred, labels, Lam,
                                             (float*)d_out);
}